// round 16
// baseline (speedup 1.0000x reference)
#include <cuda_runtime.h>
#include <cuda_fp16.h>
#include <cstdint>

#define EPSF 1e-9f
typedef unsigned long long u64;
typedef unsigned int u32;

// ---------------- persistent device scratch ----------------
__device__ __half g_h1h[256*400*256];          // conv1 out NHWC fp16  52MB
__device__ __half g_wh[256*20736];             // caps1 W [co][tap*256+ci] fp16
__device__ float g_h2[256*256*36];             // caps1 out (relu'd)  [b][co][36]
__device__ __half g_u[256u*1152*10*16];        // prediction vectors fp16  94MB
__device__ float g_blog[256*11520];            // routing logits
__device__ u32   g_ubase[11520];               // packed x-gather bases per capsule row
__device__ float g_masked[256*16];
__device__ float g_fc1[256*512];
__device__ float g_fc2[256*1024];

// ---------------- helpers ----------------
__device__ __forceinline__ void fma2(u64& acc, u64 a, u64 b) {
    asm("fma.rn.f32x2 %0, %1, %2, %0;" : "+l"(acc) : "l"(a), "l"(b));
}
__device__ __forceinline__ u64 pack2(float lo, float hi) {
    u64 r; unsigned il = __float_as_uint(lo), ih = __float_as_uint(hi);
    asm("mov.b64 %0, {%1, %2};" : "=l"(r) : "r"(il), "r"(ih));
    return r;
}
__device__ __forceinline__ u64 pack_dup(float v) {
    u64 r; unsigned iv = __float_as_uint(v);
    asm("mov.b64 %0, {%1, %1};" : "=l"(r) : "r"(iv));
    return r;
}
__device__ __forceinline__ void unpack2(u64 v, float& lo, float& hi) {
    asm("mov.b64 {%0, %1}, %2;" : "=f"(lo), "=f"(hi) : "l"(v));
}
__device__ __forceinline__ u32 smem_u32(const void* p) {
    u32 a;
    asm("{ .reg .u64 t; cvta.to.shared.u64 t, %1; cvt.u32.u64 %0, t; }" : "=r"(a) : "l"(p));
    return a;
}
__device__ __forceinline__ void cp16(u32 dst, const void* src) {
    asm volatile("cp.async.cg.shared.global [%0], [%1], 16;" :: "r"(dst), "l"(src) : "memory");
}
__device__ __forceinline__ void cp_commit() { asm volatile("cp.async.commit_group;" ::: "memory"); }
#define CP_WAIT(n) asm volatile("cp.async.wait_group %0;" :: "n"(n) : "memory")

// fp16 warp MMA m16n8k16, fp32 accum
#define MMAF16(c, a, b0, b1) \
    asm volatile("mma.sync.aligned.m16n8k16.row.col.f32.f16.f16.f32 " \
        "{%0,%1,%2,%3}, {%4,%5,%6,%7}, {%8,%9}, {%0,%1,%2,%3};" \
        : "+f"((c)[0]), "+f"((c)[1]), "+f"((c)[2]), "+f"((c)[3]) \
        : "r"((a)[0]), "r"((a)[1]), "r"((a)[2]), "r"((a)[3]), "r"(b0), "r"(b1))

__device__ __forceinline__ void ldsm4(u32& r0, u32& r1, u32& r2, u32& r3, u32 addr) {
    asm volatile("ldmatrix.sync.aligned.m8n8.x4.shared.b16 {%0,%1,%2,%3}, [%4];"
        : "=r"(r0), "=r"(r1), "=r"(r2), "=r"(r3) : "r"(addr));
}

// ---------------- weight prep: w[co][ci][9][9] fp32 -> g_wh[co][tap*256+ci] fp16 ----------------
__global__ void prep_w_kernel(const float* __restrict__ w) {
    int k  = blockIdx.x * 256 + threadIdx.x;   // 0..20735 (grid.x = 81)
    int co = blockIdx.y;
    int tap = k >> 8, ci = k & 255;
    g_wh[(size_t)co * 20736 + k] = __float2half(w[(size_t)co * 20736 + ci * 81 + tap]);
}

// ---------------- ubase prep: per row r, pack bases for qb=8r and qb=8r+4 ----------------
__global__ void prep_ubase_kernel() {
    int r = blockIdx.x * 256 + threadIdx.x;
    if (r >= 11520) return;
    int q0 = r * 8, q1 = r * 8 + 4;
    u32 b0 = (u32)((q0 / 360) * 36 + (q0 % 36));
    u32 b1 = (u32)((q1 / 360) * 36 + (q1 % 36));
    g_ubase[r] = b0 | (b1 << 16);
}

// ---------------- conv1: (B,1,28,28) -> relu -> NHWC fp16 (B,20,20,256) ----------------
__global__ __launch_bounds__(256)
void conv1_kernel(const float* __restrict__ x, const float* __restrict__ w,
                  const float* __restrict__ bias) {
    __shared__ float img[784];
    __shared__ float ws[2592];                 // layout [tap][32 co]
    __shared__ __half2 sh[400 * 16];           // [pixel][co-pair], 25.6KB
    int b = blockIdx.y, co0 = blockIdx.x * 32;
    int tid = threadIdx.x;
    for (int i = tid; i < 784; i += 256) img[i] = x[b * 784 + i];
    for (int i = tid; i < 2592; i += 256) {
        int t = i >> 5, c = i & 31;
        ws[i] = w[(co0 + c) * 81 + t];
    }
    u64 b2[16];
    #pragma unroll
    for (int c = 0; c < 16; c++) b2[c] = pack2(bias[co0 + 2*c], bias[co0 + 2*c + 1]);
    __syncthreads();

    for (int p = tid; p < 400; p += 256) {
        int oy = p / 20, ox = p % 20;
        u64 acc[16];
        #pragma unroll
        for (int c = 0; c < 16; c++) acc[c] = b2[c];
        #pragma unroll 1
        for (int dy = 0; dy < 9; dy++) {
            const float* row = img + (oy + dy) * 28 + ox;
            u64 rr[9];
            #pragma unroll
            for (int dx = 0; dx < 9; dx++) rr[dx] = pack_dup(row[dx]);
            #pragma unroll
            for (int dx = 0; dx < 9; dx++) {
                const u64* wp = (const u64*)(ws + (dy * 9 + dx) * 32);
                #pragma unroll
                for (int c = 0; c < 16; c++) fma2(acc[c], wp[c], rr[dx]);
            }
        }
        #pragma unroll
        for (int c = 0; c < 16; c++) {
            float lo, hi; unpack2(acc[c], lo, hi);
            sh[p * 16 + c] =
                __halves2half2(__float2half(fmaxf(lo, 0.f)), __float2half(fmaxf(hi, 0.f)));
        }
    }
    __syncthreads();
    __half2* dst = reinterpret_cast<__half2*>(g_h1h) + ((size_t)b * 400) * 128 + (co0 >> 1);
    for (int i = tid; i < 6400; i += 256) {
        int p = i >> 4, c = i & 15;
        dst[(size_t)p * 128 + c] = sh[i];
    }
}

// ---------------- caps1 via mma.sync fp16 + ldmatrix: C[9216,256] = A[9216,20736] @ W^T ----------------
// 256 threads (8 warps 4x2), CTA tile M=128 x N=128, grid 144.
// K-step 32, 648 steps, 2-stage cp.async, stage 20KB (80B pitch, LDSM conflict-free).
static constexpr int CSTG = 20480;          // A 128x80 + B 128x80
static constexpr u32 SMEM_C1 = 2 * CSTG;    // 40960 < 48KB

__global__ __launch_bounds__(256, 1)
void caps1_mma_kernel(const float* __restrict__ bias) {
    extern __shared__ char smem[];
    u32 sm = smem_u32(smem);
    int tid = threadIdx.x;
    int n0 = blockIdx.x * 128, m0 = blockIdx.y * 128;

    // loader: rw = tid>>1 (0..127), c2 = tid&1 handles 32B (= 16 fp16 = 2 cp16) per operand
    int rw = tid >> 1, c2 = tid & 1;
    int pl = m0 + rw;
    int pb = pl / 36, prr = pl % 36, loy = prr / 6, lox = prr % 6;
    u32 aPix = (u32)((pb * 20 + 2 * loy) * 20 + 2 * lox) * 256 + c2 * 16;
    u32 bRow = (u32)(n0 + rw) * 20736 + c2 * 16;
    u32 rowOff = (u32)(rw * 80 + c2 * 32);

    auto load_stage = [&](int s, int step) {
        u32 base = sm + s * CSTG;
        int tap = step >> 3, ci0 = (step & 7) * 32;
        int dy = tap / 9, dx = tap - dy * 9;
        u32 asrc = aPix + (u32)(dy * 20 + dx) * 256 + ci0;
        u32 bsrc = bRow + (u32)tap * 256 + ci0;
        cp16(base + rowOff,              g_h1h + asrc);
        cp16(base + rowOff + 16,         g_h1h + asrc + 8);
        cp16(base + 10240 + rowOff,      g_wh + bsrc);
        cp16(base + 10240 + rowOff + 16, g_wh + bsrc + 8);
        cp_commit();
    };

    int wid = tid >> 5, lane = tid & 31;
    int wm = wid & 3, wn = wid >> 2;               // warp tile: M 32, N 64
    int g = lane >> 2, tc = lane & 3;

    // ldmatrix per-lane address components (80B pitch)
    u32 laneA = (u32)((((lane & 7) + ((lane >> 3) & 1) * 8) * 80) + (lane >> 4) * 16);
    u32 laneB = (u32)((((lane & 7) + ((lane >> 4) & 1) * 8) * 80) + ((lane >> 3) & 1) * 16);
    u32 aWarp = (u32)(wm * 32 * 80);
    u32 bWarp = (u32)(10240 + wn * 64 * 80);

    float c[2][8][4];
    #pragma unroll
    for (int i = 0; i < 2; i++)
        #pragma unroll
        for (int j = 0; j < 8; j++)
            #pragma unroll
            for (int q = 0; q < 4; q++) c[i][j][q] = 0.f;

    load_stage(0, 0);

    #pragma unroll 1
    for (int step = 0; step < 648; step++) {
        int cur = step & 1;
        if (step + 1 < 648) { load_stage(cur ^ 1, step + 1); CP_WAIT(1); }
        else CP_WAIT(0);
        __syncthreads();

        u32 stg = sm + cur * CSTG;
        #pragma unroll
        for (int kh = 0; kh < 2; kh++) {
            u32 a[2][4];
            ldsm4(a[0][0], a[0][1], a[0][2], a[0][3], stg + aWarp + kh * 32 + laneA);
            ldsm4(a[1][0], a[1][1], a[1][2], a[1][3], stg + aWarp + 1280 + kh * 32 + laneA);
            u32 bf[8][2];
            #pragma unroll
            for (int p = 0; p < 4; p++)
                ldsm4(bf[2*p][0], bf[2*p][1], bf[2*p+1][0], bf[2*p+1][1],
                      stg + bWarp + (u32)(p * 1280) + kh * 32 + laneB);
            #pragma unroll
            for (int tn = 0; tn < 8; tn++)
                #pragma unroll
                for (int tm = 0; tm < 2; tm++)
                    MMAF16(c[tm][tn], a[tm], bf[tn][0], bf[tn][1]);
        }
        __syncthreads();
    }

    // epilogue: bias + relu -> g_h2[b][co][36]
    #pragma unroll
    for (int tm = 0; tm < 2; tm++) {
        int r0 = m0 + wm * 32 + tm * 16 + g;
        int b0i = r0 / 36, rr0 = r0 % 36;
        int r1 = r0 + 8;
        int b1i = r1 / 36, rr1 = r1 % 36;
        float* d0 = g_h2 + (size_t)b0i * 9216 + rr0;
        float* d1 = g_h2 + (size_t)b1i * 9216 + rr1;
        #pragma unroll
        for (int tn = 0; tn < 8; tn++) {
            int cc = n0 + wn * 64 + tn * 8 + tc * 2;
            float bv0 = bias[cc], bv1 = bias[cc + 1];
            d0[(size_t)cc * 36]       = fmaxf(c[tm][tn][0] + bv0, 0.f);
            d0[(size_t)(cc + 1) * 36] = fmaxf(c[tm][tn][1] + bv1, 0.f);
            d1[(size_t)cc * 36]       = fmaxf(c[tm][tn][2] + bv0, 0.f);
            d1[(size_t)(cc + 1) * 36] = fmaxf(c[tm][tn][3] + bv1, 0.f);
        }
    }
}

// ---------------- u = Wj @ x_tile, warp-per-row; x-gather base from table ----------------
__global__ __launch_bounds__(256)
void u_kernel(const float* __restrict__ W) {
    __shared__ __align__(16) float sx[9216];
    int b = blockIdx.x, chunk = blockIdx.y;
    int tid = threadIdx.x, wid = tid >> 5, lane = tid & 31;
    const float* h2b = g_h2 + (size_t)b * 9216;
    for (int i = tid; i < 9216; i += 256) sx[i] = h2b[i];
    __syncthreads();

    int half = lane & 1, mm = lane >> 1;
    __half* ub = g_u + (size_t)b * 184320;

    #pragma unroll 4
    for (int k = 0; k < 180; k++) {
        int r = chunk * 1440 + wid + 8 * k;
        float4 w4 = reinterpret_cast<const float4*>(W)[(size_t)r * 32 + lane];
        u32 bb = g_ubase[r];
        int base = half ? (int)(bb >> 16) : (int)(bb & 0xFFFFu);
        float4 x4 = *reinterpret_cast<const float4*>(&sx[base]);
        float p = w4.x * x4.x + w4.y * x4.y + w4.z * x4.z + w4.w * x4.w;
        float s = p + __shfl_xor_sync(0xFFFFFFFFu, p, 1);
        if (half == 0) ub[(size_t)r * 16 + mm] = __float2half(s);
    }
}

// ---------------- dynamic routing (3 iters), one block per batch, 576 threads ----------------
__global__ __launch_bounds__(576)
void routing_kernel(const float* __restrict__ y, const float* __restrict__ bias_r,
                    float* __restrict__ out) {
    __shared__ float spart[36 * 160];
    __shared__ float sfull[160];
    __shared__ __align__(16) float sv[160];
    __shared__ float sscale[16];
    int b = blockIdx.x, t = threadIdx.x;
    const __half* ub = g_u + (size_t)b * 184320;
    float* sb = g_blog + (size_t)b * 11520;
    int g = t >> 4, m = t & 15;

    for (int iter = 0; iter < 3; ++iter) {
        float acc[10];
        #pragma unroll
        for (int j = 0; j < 10; j++) acc[j] = 0.f;
        int i0 = g * 32;
        for (int i = i0; i < i0 + 32; i++) {
            float c[10];
            if (iter == 0) {
                #pragma unroll
                for (int j = 0; j < 10; j++) c[j] = 0.1f;
            } else {
                float mx = -1e30f;
                #pragma unroll
                for (int j = 0; j < 10; j++) { c[j] = sb[i * 10 + j]; mx = fmaxf(mx, c[j]); }
                float s = 0.f;
                #pragma unroll
                for (int j = 0; j < 10; j++) { c[j] = __expf(c[j] - mx); s += c[j]; }
                float inv = 1.f / s;
                #pragma unroll
                for (int j = 0; j < 10; j++) c[j] *= inv;
            }
            const __half* up = ub + (size_t)i * 160 + m;
            #pragma unroll
            for (int j = 0; j < 10; j++) acc[j] += c[j] * __half2float(up[j * 16]);
        }
        #pragma unroll
        for (int j = 0; j < 10; j++) spart[g * 160 + j * 16 + m] = acc[j];
        __syncthreads();

        if (t < 160) {
            float s = bias_r[t];
            #pragma unroll
            for (int g2 = 0; g2 < 36; g2++) s += spart[g2 * 160 + t];
            sfull[t] = s;
        }
        __syncthreads();
        if (t < 10) {
            float n2 = 0.f;
            #pragma unroll
            for (int mm = 0; mm < 16; mm++) { float v = sfull[t * 16 + mm]; n2 += v * v; }
            sscale[t] = (n2 / (1.f + n2)) / sqrtf(n2 + EPSF);
        }
        __syncthreads();
        if (t < 160) sv[t] = sfull[t] * sscale[t >> 4];
        __syncthreads();

        if (iter < 2) {                                   // agreement update
            for (int idx = t; idx < 11520; idx += 576) {
                int j = idx % 10;
                const __half2* up2 = (const __half2*)(ub + (size_t)idx * 16);
                const float* vj = sv + j * 16;
                float d = 0.f;
                #pragma unroll
                for (int q = 0; q < 8; q++) {
                    float2 a = __half22float2(up2[q]);
                    d += a.x * vj[2 * q] + a.y * vj[2 * q + 1];
                }
                if (iter == 0) sb[idx] = d; else sb[idx] += d;
            }
        }
        __syncthreads();
    }
    if (t < 10) {
        float n2 = 0.f;
        #pragma unroll
        for (int mm = 0; mm < 16; mm++) { float v = sv[t * 16 + mm]; n2 += v * v; }
        out[b * 10 + t] = sqrtf(n2 + EPSF);
    }
    if (t < 16) {
        float s = 0.f;
        const float* yb = y + b * 10;
        #pragma unroll
        for (int tt = 0; tt < 10; tt++) s += sv[t * 10 + tt] * yb[tt];
        g_masked[b * 16 + t] = s;
    }
}

// ---------------- FC GEMM: 32x32 tile, 2x2 per thread, BK=16 ----------------
__global__ void gemm_kernel(const float* __restrict__ Wt, const float* __restrict__ bias,
                            float* __restrict__ out, int N, int K, int which) {
    __shared__ float As[32][16];
    __shared__ float Bs[32][17];
    const float* A; float* C;
    if (which == 0)      { A = g_masked; C = g_fc1; }
    else if (which == 1) { A = g_fc1;    C = g_fc2; }
    else                 { A = g_fc2;    C = out + 2560; }
    int tx = threadIdx.x, ty = threadIdx.y;
    int tid = ty * 16 + tx;
    int n0 = blockIdx.x * 32, m0 = blockIdx.y * 32;
    float acc[2][2] = {{0.f, 0.f}, {0.f, 0.f}};

    for (int k0 = 0; k0 < K; k0 += 16) {
        #pragma unroll
        for (int i = tid; i < 512; i += 256) {
            int rr = i >> 4, kk = i & 15;
            As[rr][kk] = A[(size_t)(m0 + rr) * K + k0 + kk];
            Bs[rr][kk] = (n0 + rr < N) ? Wt[(size_t)(n0 + rr) * K + k0 + kk] : 0.f;
        }
        __syncthreads();
        #pragma unroll
        for (int kk = 0; kk < 16; kk++) {
            float a0 = As[ty * 2][kk],     a1 = As[ty * 2 + 1][kk];
            float b0 = Bs[tx * 2][kk],     b1 = Bs[tx * 2 + 1][kk];
            acc[0][0] += a0 * b0; acc[0][1] += a0 * b1;
            acc[1][0] += a1 * b0; acc[1][1] += a1 * b1;
        }
        __syncthreads();
    }
    #pragma unroll
    for (int i = 0; i < 2; i++) {
        #pragma unroll
        for (int j = 0; j < 2; j++) {
            int n = n0 + tx * 2 + j;
            if (n < N) {
                float v = acc[i][j] + bias[n];
                if (which == 2) v = 1.f / (1.f + expf(-v));
                C[(size_t)(m0 + ty * 2 + i) * N + n] = v;
            }
        }
    }
}

// ---------------- launch ----------------
extern "C" void kernel_launch(void* const* d_in, const int* in_sizes, int n_in,
                              void* d_out, int out_size) {
    (void)in_sizes; (void)n_in; (void)out_size;
    const float* x   = (const float*)d_in[0];
    const float* y   = (const float*)d_in[1];
    const float* c1w = (const float*)d_in[2];
    const float* c1b = (const float*)d_in[3];
    const float* c2w = (const float*)d_in[4];
    const float* c2b = (const float*)d_in[5];
    const float* W   = (const float*)d_in[6];
    const float* br  = (const float*)d_in[7];
    const float* f1w = (const float*)d_in[8];
    const float* f1b = (const float*)d_in[9];
    const float* f2w = (const float*)d_in[10];
    const float* f2b = (const float*)d_in[11];
    const float* f3w = (const float*)d_in[12];
    const float* f3b = (const float*)d_in[13];
    float* out = (float*)d_out;

    prep_w_kernel<<<dim3(81, 256), 256>>>(c2w);
    prep_ubase_kernel<<<45, 256>>>();
    conv1_kernel<<<dim3(8, 256), 256>>>(x, c1w, c1b);
    caps1_mma_kernel<<<dim3(2, 72), 256, SMEM_C1>>>(c2b);
    u_kernel<<<dim3(256, 8), 256>>>(W);
    routing_kernel<<<256, 576>>>(y, br, out);
    gemm_kernel<<<dim3(16, 8), dim3(16, 16)>>>(f1w, f1b, out, 512, 16, 0);
    gemm_kernel<<<dim3(32, 8), dim3(16, 16)>>>(f2w, f2b, out, 1024, 512, 1);
    gemm_kernel<<<dim3(25, 8), dim3(16, 16)>>>(f3w, f3b, out, 784, 1024, 2);
}

// round 17
// speedup vs baseline: 1.0522x; 1.0522x over previous
#include <cuda_runtime.h>
#include <cuda_fp16.h>
#include <cstdint>

#define EPSF 1e-9f
typedef unsigned long long u64;
typedef unsigned int u32;

// ---------------- persistent device scratch ----------------
__device__ __half g_h1h[256*400*256];          // conv1 out NHWC fp16  52MB
__device__ __half g_wh[256*20736];             // caps1 W [co][tap*256+ci] fp16
__device__ float g_h2[256*256*36];             // caps1 out (relu'd)  [b][co][36]
__device__ __half g_u[256u*1152*10*16];        // prediction vectors fp16  94MB
__device__ float g_blog[256*11520];            // routing logits
__device__ u32   g_ubase[11520];               // packed x-gather bases per capsule row
__device__ float g_masked[256*16];
__device__ float g_fc1[256*512];
__device__ float g_fc2[256*1024];

// ---------------- helpers ----------------
__device__ __forceinline__ void fma2(u64& acc, u64 a, u64 b) {
    asm("fma.rn.f32x2 %0, %1, %2, %0;" : "+l"(acc) : "l"(a), "l"(b));
}
__device__ __forceinline__ u64 pack2(float lo, float hi) {
    u64 r; unsigned il = __float_as_uint(lo), ih = __float_as_uint(hi);
    asm("mov.b64 %0, {%1, %2};" : "=l"(r) : "r"(il), "r"(ih));
    return r;
}
__device__ __forceinline__ u64 pack_dup(float v) {
    u64 r; unsigned iv = __float_as_uint(v);
    asm("mov.b64 %0, {%1, %1};" : "=l"(r) : "r"(iv));
    return r;
}
__device__ __forceinline__ void unpack2(u64 v, float& lo, float& hi) {
    asm("mov.b64 {%0, %1}, %2;" : "=f"(lo), "=f"(hi) : "l"(v));
}
__device__ __forceinline__ u32 smem_u32(const void* p) {
    u32 a;
    asm("{ .reg .u64 t; cvta.to.shared.u64 t, %1; cvt.u32.u64 %0, t; }" : "=r"(a) : "l"(p));
    return a;
}
__device__ __forceinline__ void cp16(u32 dst, const void* src) {
    asm volatile("cp.async.cg.shared.global [%0], [%1], 16;" :: "r"(dst), "l"(src) : "memory");
}
__device__ __forceinline__ void cp_commit() { asm volatile("cp.async.commit_group;" ::: "memory"); }
#define CP_WAIT(n) asm volatile("cp.async.wait_group %0;" :: "n"(n) : "memory")

// fp16 warp MMA m16n8k16, fp32 accum
#define MMAF16(c, a, b0, b1) \
    asm volatile("mma.sync.aligned.m16n8k16.row.col.f32.f16.f16.f32 " \
        "{%0,%1,%2,%3}, {%4,%5,%6,%7}, {%8,%9}, {%0,%1,%2,%3};" \
        : "+f"((c)[0]), "+f"((c)[1]), "+f"((c)[2]), "+f"((c)[3]) \
        : "r"((a)[0]), "r"((a)[1]), "r"((a)[2]), "r"((a)[3]), "r"(b0), "r"(b1))

__device__ __forceinline__ void ldsm4(u32& r0, u32& r1, u32& r2, u32& r3, u32 addr) {
    asm volatile("ldmatrix.sync.aligned.m8n8.x4.shared.b16 {%0,%1,%2,%3}, [%4];"
        : "=r"(r0), "=r"(r1), "=r"(r2), "=r"(r3) : "r"(addr));
}

// ---------------- weight prep: w[co][ci][9][9] fp32 -> g_wh[co][tap*256+ci] fp16 ----------------
__global__ void prep_w_kernel(const float* __restrict__ w) {
    int k  = blockIdx.x * 256 + threadIdx.x;   // 0..20735 (grid.x = 81)
    int co = blockIdx.y;
    int tap = k >> 8, ci = k & 255;
    g_wh[(size_t)co * 20736 + k] = __float2half(w[(size_t)co * 20736 + ci * 81 + tap]);
}

// ---------------- ubase prep ----------------
__global__ void prep_ubase_kernel() {
    int r = blockIdx.x * 256 + threadIdx.x;
    if (r >= 11520) return;
    int q0 = r * 8, q1 = r * 8 + 4;
    u32 b0 = (u32)((q0 / 360) * 36 + (q0 % 36));
    u32 b1 = (u32)((q1 / 360) * 36 + (q1 % 36));
    g_ubase[r] = b0 | (b1 << 16);
}

// ---------------- conv1: (B,1,28,28) -> relu -> NHWC fp16 (B,20,20,256) ----------------
__global__ __launch_bounds__(256)
void conv1_kernel(const float* __restrict__ x, const float* __restrict__ w,
                  const float* __restrict__ bias) {
    __shared__ float img[784];
    __shared__ float ws[2592];                 // layout [tap][32 co]
    __shared__ __half2 sh[400 * 16];           // [pixel][co-pair], 25.6KB
    int b = blockIdx.y, co0 = blockIdx.x * 32;
    int tid = threadIdx.x;
    for (int i = tid; i < 784; i += 256) img[i] = x[b * 784 + i];
    for (int i = tid; i < 2592; i += 256) {
        int t = i >> 5, c = i & 31;
        ws[i] = w[(co0 + c) * 81 + t];
    }
    u64 b2[16];
    #pragma unroll
    for (int c = 0; c < 16; c++) b2[c] = pack2(bias[co0 + 2*c], bias[co0 + 2*c + 1]);
    __syncthreads();

    for (int p = tid; p < 400; p += 256) {
        int oy = p / 20, ox = p % 20;
        u64 acc[16];
        #pragma unroll
        for (int c = 0; c < 16; c++) acc[c] = b2[c];
        #pragma unroll 1
        for (int dy = 0; dy < 9; dy++) {
            const float* row = img + (oy + dy) * 28 + ox;
            u64 rr[9];
            #pragma unroll
            for (int dx = 0; dx < 9; dx++) rr[dx] = pack_dup(row[dx]);
            #pragma unroll
            for (int dx = 0; dx < 9; dx++) {
                const u64* wp = (const u64*)(ws + (dy * 9 + dx) * 32);
                #pragma unroll
                for (int c = 0; c < 16; c++) fma2(acc[c], wp[c], rr[dx]);
            }
        }
        #pragma unroll
        for (int c = 0; c < 16; c++) {
            float lo, hi; unpack2(acc[c], lo, hi);
            sh[p * 16 + c] =
                __halves2half2(__float2half(fmaxf(lo, 0.f)), __float2half(fmaxf(hi, 0.f)));
        }
    }
    __syncthreads();
    __half2* dst = reinterpret_cast<__half2*>(g_h1h) + ((size_t)b * 400) * 128 + (co0 >> 1);
    for (int i = tid; i < 6400; i += 256) {
        int p = i >> 4, c = i & 15;
        dst[(size_t)p * 128 + c] = sh[i];
    }
}

// ---------------- caps1: mma.sync fp16 + ldmatrix, C[9216,256] = A[9216,20736] @ W^T ----------------
// 128 threads (4 warps 2x2), CTA tile M=64 x N=128, grid 288 (~2 CTAs/SM for overlap).
// K-step 32, 648 steps, 2-stage cp.async, ONE barrier per step.
// stage: A 64x80 = 5120 | B 128x80 = 10240 -> 15360; x2 = 30720 < 48KB.
static constexpr int CSTG = 15360;
static constexpr u32 SMEM_C1 = 2 * CSTG;

__global__ __launch_bounds__(128, 2)
void caps1_mma_kernel(const float* __restrict__ bias) {
    extern __shared__ char smem[];
    u32 sm = smem_u32(smem);
    int tid = threadIdx.x;
    int n0 = blockIdx.x * 128, m0 = blockIdx.y * 64;

    // loader: rw = tid>>1 (0..63), c2 = tid&1 handles 32B (2 cp16) per operand row
    int rw = tid >> 1, c2 = tid & 1;
    int pl = m0 + rw;
    int pb = pl / 36, prr = pl % 36, loy = prr / 6, lox = prr % 6;
    u32 aPix  = (u32)((pb * 20 + 2 * loy) * 20 + 2 * lox) * 256 + c2 * 16;
    u32 bRow0 = (u32)(n0 + rw) * 20736 + c2 * 16;
    u32 bRow1 = (u32)(n0 + rw + 64) * 20736 + c2 * 16;
    u32 aOff  = (u32)(rw * 80 + c2 * 32);
    u32 bOff0 = (u32)(5120 + rw * 80 + c2 * 32);
    u32 bOff1 = (u32)(5120 + (rw + 64) * 80 + c2 * 32);

    auto load_stage = [&](int s, int step) {
        u32 base = sm + s * CSTG;
        int tap = step >> 3, ci0 = (step & 7) * 32;
        int dy = tap / 9, dx = tap - dy * 9;
        u32 asrc = aPix + (u32)(dy * 20 + dx) * 256 + ci0;
        u32 bs = (u32)tap * 256 + ci0;
        cp16(base + aOff,       g_h1h + asrc);
        cp16(base + aOff + 16,  g_h1h + asrc + 8);
        cp16(base + bOff0,      g_wh + bRow0 + bs);
        cp16(base + bOff0 + 16, g_wh + bRow0 + bs + 8);
        cp16(base + bOff1,      g_wh + bRow1 + bs);
        cp16(base + bOff1 + 16, g_wh + bRow1 + bs + 8);
        cp_commit();
    };

    int wid = tid >> 5, lane = tid & 31;
    int wm = wid & 1, wn = wid >> 1;               // warp tile: M 32, N 64
    int g = lane >> 2, tc = lane & 3;

    // ldmatrix per-lane address components (80B pitch)
    u32 laneA = (u32)((((lane & 7) + ((lane >> 3) & 1) * 8) * 80) + (lane >> 4) * 16);
    u32 laneB = (u32)((((lane & 7) + ((lane >> 4) & 1) * 8) * 80) + ((lane >> 3) & 1) * 16);
    u32 aWarp = (u32)(wm * 32 * 80);
    u32 bWarp = (u32)(5120 + wn * 64 * 80);

    float c[2][8][4];
    #pragma unroll
    for (int i = 0; i < 2; i++)
        #pragma unroll
        for (int j = 0; j < 8; j++)
            #pragma unroll
            for (int q = 0; q < 4; q++) c[i][j][q] = 0.f;

    load_stage(0, 0);

    #pragma unroll 1
    for (int step = 0; step < 648; step++) {
        int cur = step & 1;
        CP_WAIT(0);              // stage cur landed (only group in flight)
        __syncthreads();         // all warps done reading stage cur^1 (previous step)
        if (step + 1 < 648) load_stage(cur ^ 1, step + 1);

        u32 stg = sm + cur * CSTG;
        #pragma unroll
        for (int kh = 0; kh < 2; kh++) {
            u32 a[2][4];
            ldsm4(a[0][0], a[0][1], a[0][2], a[0][3], stg + aWarp + kh * 32 + laneA);
            ldsm4(a[1][0], a[1][1], a[1][2], a[1][3], stg + aWarp + 1280 + kh * 32 + laneA);
            u32 bf[8][2];
            #pragma unroll
            for (int p = 0; p < 4; p++)
                ldsm4(bf[2*p][0], bf[2*p][1], bf[2*p+1][0], bf[2*p+1][1],
                      stg + bWarp + (u32)(p * 1280) + kh * 32 + laneB);
            #pragma unroll
            for (int tn = 0; tn < 8; tn++)
                #pragma unroll
                for (int tm = 0; tm < 2; tm++)
                    MMAF16(c[tm][tn], a[tm], bf[tn][0], bf[tn][1]);
        }
    }
    __syncthreads();

    // epilogue: bias + relu -> g_h2[b][co][36]
    #pragma unroll
    for (int tm = 0; tm < 2; tm++) {
        int r0 = m0 + wm * 32 + tm * 16 + g;
        int b0i = r0 / 36, rr0 = r0 % 36;
        int r1 = r0 + 8;
        int b1i = r1 / 36, rr1 = r1 % 36;
        float* d0 = g_h2 + (size_t)b0i * 9216 + rr0;
        float* d1 = g_h2 + (size_t)b1i * 9216 + rr1;
        #pragma unroll
        for (int tn = 0; tn < 8; tn++) {
            int cc = n0 + wn * 64 + tn * 8 + tc * 2;
            float bv0 = bias[cc], bv1 = bias[cc + 1];
            d0[(size_t)cc * 36]       = fmaxf(c[tm][tn][0] + bv0, 0.f);
            d0[(size_t)(cc + 1) * 36] = fmaxf(c[tm][tn][1] + bv1, 0.f);
            d1[(size_t)cc * 36]       = fmaxf(c[tm][tn][2] + bv0, 0.f);
            d1[(size_t)(cc + 1) * 36] = fmaxf(c[tm][tn][3] + bv1, 0.f);
        }
    }
}

// ---------------- u = Wj @ x_tile, warp-per-row; x-gather base from table ----------------
__global__ __launch_bounds__(256)
void u_kernel(const float* __restrict__ W) {
    __shared__ __align__(16) float sx[9216];
    int b = blockIdx.x, chunk = blockIdx.y;
    int tid = threadIdx.x, wid = tid >> 5, lane = tid & 31;
    const float* h2b = g_h2 + (size_t)b * 9216;
    for (int i = tid; i < 9216; i += 256) sx[i] = h2b[i];
    __syncthreads();

    int half = lane & 1, mm = lane >> 1;
    __half* ub = g_u + (size_t)b * 184320;

    #pragma unroll 4
    for (int k = 0; k < 180; k++) {
        int r = chunk * 1440 + wid + 8 * k;
        float4 w4 = reinterpret_cast<const float4*>(W)[(size_t)r * 32 + lane];
        u32 bb = g_ubase[r];
        int base = half ? (int)(bb >> 16) : (int)(bb & 0xFFFFu);
        float4 x4 = *reinterpret_cast<const float4*>(&sx[base]);
        float p = w4.x * x4.x + w4.y * x4.y + w4.z * x4.z + w4.w * x4.w;
        float s = p + __shfl_xor_sync(0xFFFFFFFFu, p, 1);
        if (half == 0) ub[(size_t)r * 16 + mm] = __float2half(s);
    }
}

// ---------------- dynamic routing (3 iters), one block per batch, 576 threads ----------------
__global__ __launch_bounds__(576)
void routing_kernel(const float* __restrict__ y, const float* __restrict__ bias_r,
                    float* __restrict__ out) {
    __shared__ float spart[36 * 160];
    __shared__ float sfull[160];
    __shared__ __align__(16) float sv[160];
    __shared__ float sscale[16];
    int b = blockIdx.x, t = threadIdx.x;
    const __half* ub = g_u + (size_t)b * 184320;
    float* sb = g_blog + (size_t)b * 11520;
    int g = t >> 4, m = t & 15;

    for (int iter = 0; iter < 3; ++iter) {
        float acc[10];
        #pragma unroll
        for (int j = 0; j < 10; j++) acc[j] = 0.f;
        int i0 = g * 32;
        for (int i = i0; i < i0 + 32; i++) {
            float c[10];
            if (iter == 0) {
                #pragma unroll
                for (int j = 0; j < 10; j++) c[j] = 0.1f;
            } else {
                float mx = -1e30f;
                #pragma unroll
                for (int j = 0; j < 10; j++) { c[j] = sb[i * 10 + j]; mx = fmaxf(mx, c[j]); }
                float s = 0.f;
                #pragma unroll
                for (int j = 0; j < 10; j++) { c[j] = __expf(c[j] - mx); s += c[j]; }
                float inv = 1.f / s;
                #pragma unroll
                for (int j = 0; j < 10; j++) c[j] *= inv;
            }
            const __half* up = ub + (size_t)i * 160 + m;
            #pragma unroll
            for (int j = 0; j < 10; j++) acc[j] += c[j] * __half2float(up[j * 16]);
        }
        #pragma unroll
        for (int j = 0; j < 10; j++) spart[g * 160 + j * 16 + m] = acc[j];
        __syncthreads();

        if (t < 160) {
            float s = bias_r[t];
            #pragma unroll
            for (int g2 = 0; g2 < 36; g2++) s += spart[g2 * 160 + t];
            sfull[t] = s;
        }
        __syncthreads();
        if (t < 10) {
            float n2 = 0.f;
            #pragma unroll
            for (int mm = 0; mm < 16; mm++) { float v = sfull[t * 16 + mm]; n2 += v * v; }
            sscale[t] = (n2 / (1.f + n2)) / sqrtf(n2 + EPSF);
        }
        __syncthreads();
        if (t < 160) sv[t] = sfull[t] * sscale[t >> 4];
        __syncthreads();

        if (iter < 2) {                                   // agreement update
            for (int idx = t; idx < 11520; idx += 576) {
                int j = idx % 10;
                const __half2* up2 = (const __half2*)(ub + (size_t)idx * 16);
                const float* vj = sv + j * 16;
                float d = 0.f;
                #pragma unroll
                for (int q = 0; q < 8; q++) {
                    float2 a = __half22float2(up2[q]);
                    d += a.x * vj[2 * q] + a.y * vj[2 * q + 1];
                }
                if (iter == 0) sb[idx] = d; else sb[idx] += d;
            }
        }
        __syncthreads();
    }
    if (t < 10) {
        float n2 = 0.f;
        #pragma unroll
        for (int mm = 0; mm < 16; mm++) { float v = sv[t * 16 + mm]; n2 += v * v; }
        out[b * 10 + t] = sqrtf(n2 + EPSF);
    }
    if (t < 16) {
        float s = 0.f;
        const float* yb = y + b * 10;
        #pragma unroll
        for (int tt = 0; tt < 10; tt++) s += sv[t * 10 + tt] * yb[tt];
        g_masked[b * 16 + t] = s;
    }
}

// ---------------- FC GEMM: 32x32 tile, 2x2 per thread, BK=16 ----------------
__global__ void gemm_kernel(const float* __restrict__ Wt, const float* __restrict__ bias,
                            float* __restrict__ out, int N, int K, int which) {
    __shared__ float As[32][16];
    __shared__ float Bs[32][17];
    const float* A; float* C;
    if (which == 0)      { A = g_masked; C = g_fc1; }
    else if (which == 1) { A = g_fc1;    C = g_fc2; }
    else                 { A = g_fc2;    C = out + 2560; }
    int tx = threadIdx.x, ty = threadIdx.y;
    int tid = ty * 16 + tx;
    int n0 = blockIdx.x * 32, m0 = blockIdx.y * 32;
    float acc[2][2] = {{0.f, 0.f}, {0.f, 0.f}};

    for (int k0 = 0; k0 < K; k0 += 16) {
        #pragma unroll
        for (int i = tid; i < 512; i += 256) {
            int rr = i >> 4, kk = i & 15;
            As[rr][kk] = A[(size_t)(m0 + rr) * K + k0 + kk];
            Bs[rr][kk] = (n0 + rr < N) ? Wt[(size_t)(n0 + rr) * K + k0 + kk] : 0.f;
        }
        __syncthreads();
        #pragma unroll
        for (int kk = 0; kk < 16; kk++) {
            float a0 = As[ty * 2][kk],     a1 = As[ty * 2 + 1][kk];
            float b0 = Bs[tx * 2][kk],     b1 = Bs[tx * 2 + 1][kk];
            acc[0][0] += a0 * b0; acc[0][1] += a0 * b1;
            acc[1][0] += a1 * b0; acc[1][1] += a1 * b1;
        }
        __syncthreads();
    }
    #pragma unroll
    for (int i = 0; i < 2; i++) {
        #pragma unroll
        for (int j = 0; j < 2; j++) {
            int n = n0 + tx * 2 + j;
            if (n < N) {
                float v = acc[i][j] + bias[n];
                if (which == 2) v = 1.f / (1.f + expf(-v));
                C[(size_t)(m0 + ty * 2 + i) * N + n] = v;
            }
        }
    }
}

// ---------------- launch ----------------
extern "C" void kernel_launch(void* const* d_in, const int* in_sizes, int n_in,
                              void* d_out, int out_size) {
    (void)in_sizes; (void)n_in; (void)out_size;
    const float* x   = (const float*)d_in[0];
    const float* y   = (const float*)d_in[1];
    const float* c1w = (const float*)d_in[2];
    const float* c1b = (const float*)d_in[3];
    const float* c2w = (const float*)d_in[4];
    const float* c2b = (const float*)d_in[5];
    const float* W   = (const float*)d_in[6];
    const float* br  = (const float*)d_in[7];
    const float* f1w = (const float*)d_in[8];
    const float* f1b = (const float*)d_in[9];
    const float* f2w = (const float*)d_in[10];
    const float* f2b = (const float*)d_in[11];
    const float* f3w = (const float*)d_in[12];
    const float* f3b = (const float*)d_in[13];
    float* out = (float*)d_out;

    prep_w_kernel<<<dim3(81, 256), 256>>>(c2w);
    prep_ubase_kernel<<<45, 256>>>();
    conv1_kernel<<<dim3(8, 256), 256>>>(x, c1w, c1b);
    caps1_mma_kernel<<<dim3(2, 144), 128, SMEM_C1>>>(c2b);
    u_kernel<<<dim3(256, 8), 256>>>(W);
    routing_kernel<<<256, 576>>>(y, br, out);
    gemm_kernel<<<dim3(16, 8), dim3(16, 16)>>>(f1w, f1b, out, 512, 16, 0);
    gemm_kernel<<<dim3(32, 8), dim3(16, 16)>>>(f2w, f2b, out, 1024, 512, 1);
    gemm_kernel<<<dim3(25, 8), dim3(16, 16)>>>(f3w, f3b, out, 784, 1024, 2);
}